// round 15
// baseline (speedup 1.0000x reference)
#include <cuda_runtime.h>
#include <cuda_bf16.h>

#define NN 100000
#define EE 1600000
#define BB 64
#define BNEPS 1e-5f
#define GRID 592

// g_M layout per layer: M1[din], then M2 rows padded to (din+1)
#define M1OFF 0
#define M2OFF 16
#define M3OFF 304
#define MTOT 1392

// ---------------- scratch ----------------
__device__ __align__(16) float g_P[(size_t)NN * 4];
__device__ __align__(16) __nv_bfloat16 g_Pb[(size_t)NN * 32];
__device__ __align__(16) float g_A[(size_t)NN * 32];
__device__ __align__(16) int g_degi[NN];
__device__ int g_rowptr[NN + 1];
__device__ int g_cursor[NN];
__device__ int g_src[EE];
__device__ int g_batch[NN];
__device__ float g_dis[NN];
__device__ float g_stats[128];
__device__ float g_M[MTOT];
__device__ int g_bsum[98];
__device__ int g_boff[98];
__device__ __align__(16) float g_pool[BB * 64];
__device__ int g_cnti[BB];
// sync state (all 0 at entry of every replay; self-resetting)
__device__ int s_cA, s_fA, s_cB, s_fB, s_fC, s_cD, s_fD, s_cF;
__device__ int l1_c, l1_f, l1_c2;
__device__ int L2_cA, L2_fA, L2_cB, L2_fB, L2_cC;
__device__ int L3_cA, L3_fA, L3_cB, L3_fB, L3_cC;

__device__ __forceinline__ int detect_e64(const void* ei) {
    const long long* p = (const long long*)ei;
    int ok = 1;
    for (int i = 0; i < 64; i++) {
        long long v = p[i];
        if (v < 0 || v >= NN) ok = 0;
    }
    return ok;
}

// block-wide arrive + wait on a global counter/flag pair
#define ARRIVE_AND_WAIT(cnt, flag) do {                                        \
    __threadfence(); __syncthreads();                                          \
    if (threadIdx.x == 0) {                                                    \
        if (atomicAdd(&(cnt), 1) == (int)gridDim.x - 1)                        \
            *((volatile int*)&(flag)) = 1;                                     \
        while (*((volatile int*)&(flag)) == 0) {}                              \
    }                                                                          \
    __syncthreads(); __threadfence();                                          \
} while (0)

// ---------------- BN solve from moments ----------------
__device__ __forceinline__ void solve_body(const float* __restrict__ W,
                                           const float* __restrict__ bias,
                                           const float* __restrict__ gam,
                                           const float* __restrict__ bet,
                                           int moff, int din, int dout, int t) {
    if (t >= dout) return;
    float m1w = 0.0f;
    for (int k = 0; k < din; k++) m1w += g_M[moff + k] * W[k * dout + t];
    float q = 0.0f;
    for (int j = 0; j < din; j++) {
        float wj = W[j * dout + t];
        const float* mrow = &g_M[moff + din + j * (din + 1)];
        for (int k = 0; k < din; k++) q += wj * mrow[k] * W[k * dout + t];
    }
    float bc = bias[t];
    const float inv_n = 1.0f / NN;
    float mu  = m1w * inv_n + bc;
    float ex2 = q * inv_n + 2.0f * bc * m1w * inv_n + bc * bc;
    float var = ex2 - mu * mu;
    float scale = gam[t] * rsqrtf(var + BNEPS);
    g_stats[t] = scale;
    g_stats[64 + t] = (bc - mu) * scale + bet[t];
}

// ---------------- persistent CSR build: hist -> scan -> fill ----------------
__global__ void __launch_bounds__(256, 4) csr_kernel(const void* ei, const void* batch,
                                                     const float* __restrict__ x) {
    int t = threadIdx.x, bid = blockIdx.x, G = gridDim.x;
    __shared__ int s64, s64b;
    __shared__ int ch[BB];
    if (t == 0) s64 = detect_e64(ei);
    if (t == 1) {
        const long long* q = (const long long*)batch;
        int okb = 1;
        for (int i2 = 0; i2 < 32; i2++) {
            long long v = q[NN / 4 + i2];
            if (v < 0 || v >= BB) okb = 0;
        }
        s64b = okb;
    }
    if (t < BB) ch[t] = 0;
    __syncthreads();
    int e64 = s64, b64 = s64b;
    for (int e = bid * 256 + t; e < EE; e += G * 256) {
        int c = e64 ? (int)((const long long*)ei)[EE + e] : ((const int*)ei)[EE + e];
        atomicAdd(&g_degi[c], 1);
    }
    for (int i = bid * 256 + t; i < NN; i += G * 256) {
        int b = b64 ? (int)((const long long*)batch)[i] : ((const int*)batch)[i];
        g_batch[i] = b;
        atomicAdd(&ch[b], 1);
    }
    __syncthreads();
    if (t < BB && ch[t]) atomicAdd(&g_cnti[t], ch[t]);
    ARRIVE_AND_WAIT(s_cA, s_fA);
    __shared__ int sh1[256];
    if (bid < 98) {
        int base = bid * 1024 + t * 4;
        int sum = 0;
        if (base + 3 < NN) {
            int4 d = *(const int4*)&g_degi[base];
            sum = d.x + d.y + d.z + d.w;
        } else {
            for (int u = 0; u < 4; u++) if (base + u < NN) sum += g_degi[base + u];
        }
        sh1[t] = sum;
        __syncthreads();
        for (int off = 128; off > 0; off >>= 1) {
            if (t < off) sh1[t] += sh1[t + off];
            __syncthreads();
        }
        if (t == 0) g_bsum[bid] = sh1[0];
    }
    ARRIVE_AND_WAIT(s_cB, s_fB);
    if (bid == 0) {
        __shared__ int s2[128];
        int v = 0;
        if (t < 128) { v = (t < 98) ? g_bsum[t] : 0; s2[t] = v; }
        __syncthreads();
        for (int off = 1; off < 128; off <<= 1) {
            int u = (t < 128 && t >= off) ? s2[t - off] : 0;
            __syncthreads();
            if (t < 128) s2[t] += u;
            __syncthreads();
        }
        if (t < 98) g_boff[t] = s2[t] - v;
        if (t == 127) g_rowptr[NN] = s2[127];
        __threadfence(); __syncthreads();
        if (t == 0) *((volatile int*)&s_fC) = 1;
    }
    if (t == 0) { while (*((volatile int*)&s_fC) == 0) {} }
    __syncthreads(); __threadfence();
    __shared__ int sh3[256];
    if (bid < 98) {
        int base = bid * 1024 + t * 4;
        int d0 = 0, d1 = 0, d2 = 0, d3 = 0;
        if (base + 3 < NN) {
            int4 d = *(const int4*)&g_degi[base];
            d0 = d.x; d1 = d.y; d2 = d.z; d3 = d.w;
            *(int4*)&g_degi[base] = make_int4(0, 0, 0, 0);
        } else {
            if (base + 0 < NN) { d0 = g_degi[base + 0]; g_degi[base + 0] = 0; }
            if (base + 1 < NN) { d1 = g_degi[base + 1]; g_degi[base + 1] = 0; }
            if (base + 2 < NN) { d2 = g_degi[base + 2]; g_degi[base + 2] = 0; }
            if (base + 3 < NN) { d3 = g_degi[base + 3]; g_degi[base + 3] = 0; }
        }
        int tsum = d0 + d1 + d2 + d3;
        sh3[t] = tsum;
        __syncthreads();
        for (int off = 1; off < 256; off <<= 1) {
            int u = (t >= off) ? sh3[t - off] : 0;
            __syncthreads();
            sh3[t] += u;
            __syncthreads();
        }
        int off = g_boff[bid] + sh3[t] - tsum;
        int pre[4] = {off, off + d0, off + d0 + d1, off + d0 + d1 + d2};
        int dd[4] = {d0, d1, d2, d3};
        for (int u = 0; u < 4; u++) {
            int idx = base + u;
            if (idx < NN) {
                g_rowptr[idx] = pre[u];
                g_cursor[idx] = pre[u];
                g_dis[idx] = rsqrtf((float)(dd[u] + 1));
            }
        }
    }
    ARRIVE_AND_WAIT(s_cD, s_fD);
    for (int e = bid * 256 + t; e < EE; e += G * 256) {
        int r, c;
        if (e64) {
            const long long* p = (const long long*)ei;
            r = (int)p[e]; c = (int)p[EE + e];
        } else {
            const int* p = (const int*)ei;
            r = p[e]; c = p[EE + e];
        }
        int pos = atomicAdd(&g_cursor[c], 1);
        g_src[pos] = r;
    }
    for (int i = bid * 256 + t; i < NN; i += G * 256) {
        float d = g_dis[i];
        ((float4*)g_P)[i] = make_float4(x[3 * i] * d, x[3 * i + 1] * d, x[3 * i + 2] * d, 0.0f);
    }
    __threadfence(); __syncthreads();
    if (t == 0) {
        if (atomicAdd(&s_cF, 1) == G - 1) {
            s_cA = 0; s_fA = 0; s_cB = 0; s_fB = 0; s_fC = 0; s_cD = 0; s_fD = 0; s_cF = 0;
            __threadfence();
        }
    }
}

// ---------------- layer 1: gather + moments + solve + fused output ----------------
__global__ void __launch_bounds__(256, 4) layer1_kernel(const float* __restrict__ W,
                                                        const float* __restrict__ bias,
                                                        const float* __restrict__ gam,
                                                        const float* __restrict__ bet) {
    __shared__ float Wsh[48];
    __shared__ int last;
    int t = threadIdx.x;
    if (t < 48) Wsh[t] = W[t];
    int i = blockIdx.x * 256 + t;
    float4 acc = make_float4(0, 0, 0, 0);
    float d = 0.0f;
    if (i < NN) {
        const float4* __restrict__ P4 = (const float4*)g_P;
        acc = P4[i];
        int s = g_rowptr[i], e = g_rowptr[i + 1];
        int j = s;
        for (; j + 4 <= e; j += 4) {
            int r0 = g_src[j], r1 = g_src[j + 1], r2 = g_src[j + 2], r3 = g_src[j + 3];
            float4 v0 = P4[r0];
            float4 v1 = P4[r1];
            float4 v2 = P4[r2];
            float4 v3 = P4[r3];
            acc.x += (v0.x + v1.x) + (v2.x + v3.x);
            acc.y += (v0.y + v1.y) + (v2.y + v3.y);
            acc.z += (v0.z + v1.z) + (v2.z + v3.z);
            acc.w += (v0.w + v1.w) + (v2.w + v3.w);
        }
        for (; j < e; j++) {
            float4 v = P4[g_src[j]];
            acc.x += v.x; acc.y += v.y; acc.z += v.z; acc.w += v.w;
        }
        d = g_dis[i];
    }
    float s0 = acc.x * d, s1 = acc.y * d, s2 = acc.z * d;
    float m[12];
    m[0] = s0; m[1] = s1; m[2] = s2;
    m[3] = s0 * s0; m[4] = s0 * s1; m[5] = s0 * s2;
    m[6] = s1 * s0; m[7] = s1 * s1; m[8] = s1 * s2;
    m[9] = s2 * s0; m[10] = s2 * s1; m[11] = s2 * s2;
#pragma unroll
    for (int u = 0; u < 12; u++)
        for (int o = 16; o > 0; o >>= 1)
            m[u] += __shfl_down_sync(0xffffffffu, m[u], o);
    if ((t & 31) == 0) {
#pragma unroll
        for (int u = 0; u < 3; u++) atomicAdd(&g_M[M1OFF + u], m[u]);
#pragma unroll
        for (int u = 0; u < 9; u++)
            atomicAdd(&g_M[M1OFF + 3 + (u / 3) * 4 + (u % 3)], m[3 + u]);
    }
    __threadfence(); __syncthreads();
    if (t == 0) last = (atomicAdd(&l1_c, 1) == (int)gridDim.x - 1);
    __syncthreads();
    if (last) {
        solve_body(Wsh, bias, gam, bet, M1OFF, 3, 16, t);
        __syncthreads();
        if (t < 16) g_M[M1OFF + t] = 0.0f;
        __threadfence(); __syncthreads();
        if (t == 0) *((volatile int*)&l1_f) = 1;
    }
    if (t == 0) { while (*((volatile int*)&l1_f) == 0) {} }
    __syncthreads(); __threadfence();
    if (i < NN) {
        float hv[16];
#pragma unroll
        for (int c = 0; c < 16; c++) {
            float dot = acc.x * Wsh[c] + acc.y * Wsh[16 + c] + acc.z * Wsh[32 + c];
            hv[c] = fmaxf(d * dot * g_stats[c] + g_stats[64 + c], 0.0f) * d;
        }
        __nv_bfloat162 pk[8];
#pragma unroll
        for (int u = 0; u < 8; u++) pk[u] = __floats2bfloat162_rn(hv[2 * u], hv[2 * u + 1]);
        uint4* dst = (uint4*)(g_Pb + (size_t)i * 16);
        dst[0] = *(uint4*)&pk[0];
        dst[1] = *(uint4*)&pk[4];
    }
    __syncthreads();
    if (t == 0) {
        if (atomicAdd(&l1_c2, 1) == (int)gridDim.x - 1) {
            l1_c = 0; l1_c2 = 0; l1_f = 0; __threadfence();
        }
    }
}

// ---------------- bf16 gather phase (grid-stride; hot loop unchanged) ----------------
template <int CH>
__device__ __forceinline__ void gather_phase(int t) {
    constexpr int TPN = CH / 8;
    const uint4* __restrict__ Pb = (const uint4*)g_Pb;
    for (int idx = blockIdx.x * 256 + t; idx < NN * TPN; idx += (int)gridDim.x * 256) {
        int i = idx / TPN;
        int sub = idx % TPN;
        float acc[8];
        {
            uint4 v = Pb[(size_t)i * TPN + sub];
            const __nv_bfloat162* h = (const __nv_bfloat162*)&v;
#pragma unroll
            for (int u = 0; u < 4; u++) {
                float2 f = __bfloat1622float2(h[u]);
                acc[2 * u] = f.x; acc[2 * u + 1] = f.y;
            }
        }
        int s = g_rowptr[i], e = g_rowptr[i + 1];
        int j = s;
        for (; j + 4 <= e; j += 4) {
            int r0 = g_src[j], r1 = g_src[j + 1], r2 = g_src[j + 2], r3 = g_src[j + 3];
            uint4 v0 = Pb[(size_t)r0 * TPN + sub];
            uint4 v1 = Pb[(size_t)r1 * TPN + sub];
            uint4 v2 = Pb[(size_t)r2 * TPN + sub];
            uint4 v3 = Pb[(size_t)r3 * TPN + sub];
            const __nv_bfloat162* h0 = (const __nv_bfloat162*)&v0;
            const __nv_bfloat162* h1 = (const __nv_bfloat162*)&v1;
            const __nv_bfloat162* h2 = (const __nv_bfloat162*)&v2;
            const __nv_bfloat162* h3 = (const __nv_bfloat162*)&v3;
#pragma unroll
            for (int u = 0; u < 4; u++) {
                float2 f0 = __bfloat1622float2(h0[u]);
                float2 f1 = __bfloat1622float2(h1[u]);
                float2 f2 = __bfloat1622float2(h2[u]);
                float2 f3 = __bfloat1622float2(h3[u]);
                acc[2 * u]     += (f0.x + f1.x) + (f2.x + f3.x);
                acc[2 * u + 1] += (f0.y + f1.y) + (f2.y + f3.y);
            }
        }
        for (; j < e; j++) {
            uint4 v = Pb[(size_t)g_src[j] * TPN + sub];
            const __nv_bfloat162* h = (const __nv_bfloat162*)&v;
#pragma unroll
            for (int u = 0; u < 4; u++) {
                float2 f = __bfloat1622float2(h[u]);
                acc[2 * u] += f.x; acc[2 * u + 1] += f.y;
            }
        }
        float4* Ao = (float4*)(g_A + (size_t)i * CH + sub * 8);
        Ao[0] = make_float4(acc[0], acc[1], acc[2], acc[3]);
        Ao[1] = make_float4(acc[4], acc[5], acc[6], acc[7]);
    }
}

// ---------------- moments phase ----------------
template <int DIN, int MOFF>
__device__ __forceinline__ void mom_phase(int t) {
    constexpr int RPW = 32 / DIN;
    constexpr int NIT = DIN + DIN * (DIN + 1);
    __shared__ float Msh[NIT];
    for (int u = t; u < NIT; u += 256) Msh[u] = 0.0f;
    __syncthreads();
    int lane = t & 31, w = t >> 5;
    int gw = blockIdx.x * 8 + w;
    int sub = lane / DIN;
    int ch = lane % DIN;
    float acc1 = 0.0f;
    float acc2[DIN];
#pragma unroll
    for (int k = 0; k < DIN; k++) acc2[k] = 0.0f;
    int stride = gridDim.x * 8 * RPW;
    for (int r0 = gw * RPW; r0 < NN; r0 += stride) {
        int r = r0 + sub;
        float s = g_A[(size_t)r * DIN + ch] * g_dis[r];
        acc1 += s;
#pragma unroll
        for (int k = 0; k < DIN; k++)
            acc2[k] += s * __shfl_sync(0xffffffffu, s, k, DIN);
    }
    atomicAdd(&Msh[ch], acc1);
#pragma unroll
    for (int k = 0; k < DIN; k++)
        atomicAdd(&Msh[DIN + ch * (DIN + 1) + k], acc2[k]);
    __syncthreads();
    for (int u = t; u < NIT; u += 256) atomicAdd(&g_M[MOFF + u], Msh[u]);
}

// ---------------- layer 2: gather + moments + solve + fused output ----------------
__global__ void __launch_bounds__(256, 4) layer2_kernel(const float* __restrict__ W,
                                                        const float* __restrict__ bias,
                                                        const float* __restrict__ gam,
                                                        const float* __restrict__ bet) {
    __shared__ float Wsh[16 * 32];
    __shared__ int last;
    int t = threadIdx.x;
    for (int u = t; u < 512; u += 256) Wsh[u] = W[u];
    gather_phase<16>(t);
    ARRIVE_AND_WAIT(L2_cA, L2_fA);
    mom_phase<16, M2OFF>(t);
    __threadfence(); __syncthreads();
    if (t == 0) last = (atomicAdd(&L2_cB, 1) == (int)gridDim.x - 1);
    __syncthreads();
    if (last) {
        solve_body(Wsh, bias, gam, bet, M2OFF, 16, 32, t);
        __syncthreads();
        for (int u = t; u < 288; u += 256) g_M[M2OFF + u] = 0.0f;
        __threadfence(); __syncthreads();
        if (t == 0) *((volatile int*)&L2_fB) = 1;
    }
    if (t == 0) { while (*((volatile int*)&L2_fB) == 0) {} }
    __syncthreads(); __threadfence();
    int c = t & 31;
    float scale = g_stats[c], off = g_stats[64 + c];
    int rstart = blockIdx.x * 8 + (t >> 5);
    int rstride = gridDim.x * 8;
    for (int i = rstart; i < NN; i += rstride) {
        const float4* a4 = (const float4*)(g_A + (size_t)i * 16);
        float dot = 0.0f;
#pragma unroll
        for (int kk = 0; kk < 4; kk++) {
            float4 av = a4[kk];
            int kb = kk * 4;
            dot += av.x * Wsh[(kb + 0) * 32 + c];
            dot += av.y * Wsh[(kb + 1) * 32 + c];
            dot += av.z * Wsh[(kb + 2) * 32 + c];
            dot += av.w * Wsh[(kb + 3) * 32 + c];
        }
        float d = g_dis[i];
        float h = fmaxf(d * dot * scale + off, 0.0f);
        g_Pb[(size_t)i * 32 + c] = __float2bfloat16(h * d);
    }
    __syncthreads();
    if (t == 0) {
        if (atomicAdd(&L2_cC, 1) == (int)gridDim.x - 1) {
            L2_cA = 0; L2_fA = 0; L2_cB = 0; L2_fB = 0; L2_cC = 0; __threadfence();
        }
    }
}

// ---------------- layer 3: gather + moments + solve + fused bn/relu -> pool -> FC ----------------
__global__ void __launch_bounds__(256, 4) layer3_kernel(const float* __restrict__ W,
                                                        const float* __restrict__ bias,
                                                        const float* __restrict__ gam,
                                                        const float* __restrict__ bet,
                                                        const float* __restrict__ fcW,
                                                        const float* __restrict__ fcb,
                                                        float* __restrict__ out) {
    __shared__ float Wsh[32 * 64];
    __shared__ float pool[BB * 64];
    __shared__ int last;
    int t = threadIdx.x;
    for (int u = t; u < 2048; u += 256) Wsh[u] = W[u];
    for (int u = t; u < BB * 64; u += 256) pool[u] = 0.0f;
    gather_phase<32>(t);
    ARRIVE_AND_WAIT(L3_cA, L3_fA);
    mom_phase<32, M3OFF>(t);
    __threadfence(); __syncthreads();
    if (t == 0) last = (atomicAdd(&L3_cB, 1) == (int)gridDim.x - 1);
    __syncthreads();
    if (last) {
        solve_body(Wsh, bias, gam, bet, M3OFF, 32, 64, t);
        __syncthreads();
        for (int u = t; u < 1088; u += 256) g_M[M3OFF + u] = 0.0f;
        __threadfence(); __syncthreads();
        if (t == 0) *((volatile int*)&L3_fB) = 1;
    }
    if (t == 0) { while (*((volatile int*)&L3_fB) == 0) {} }
    __syncthreads(); __threadfence();
    int c = t & 63;
    float scale = g_stats[c], off = g_stats[64 + c];
    int rstart = blockIdx.x * 4 + (t >> 6);
    int rstride = gridDim.x * 4;
    for (int i = rstart; i < NN; i += rstride) {
        const float4* a4 = (const float4*)(g_A + (size_t)i * 32);
        float dot = 0.0f;
#pragma unroll
        for (int kk = 0; kk < 8; kk++) {
            float4 av = a4[kk];
            int kb = kk * 4;
            dot += av.x * Wsh[(kb + 0) * 64 + c];
            dot += av.y * Wsh[(kb + 1) * 64 + c];
            dot += av.z * Wsh[(kb + 2) * 64 + c];
            dot += av.w * Wsh[(kb + 3) * 64 + c];
        }
        float d = g_dis[i];
        float h = fmaxf(d * dot * scale + off, 0.0f);
        atomicAdd(&pool[g_batch[i] * 64 + c], h);
    }
    __syncthreads();
    for (int u = t; u < BB * 16; u += 256) {
        float4 v = ((const float4*)pool)[u];
        float* dst = g_pool + u * 4;
        unsigned long long p = (unsigned long long)__cvta_generic_to_global(dst);
        asm volatile("red.global.add.v4.f32 [%0], {%1,%2,%3,%4};"
                     :: "l"(p), "f"(v.x), "f"(v.y), "f"(v.z), "f"(v.w) : "memory");
    }
    __threadfence(); __syncthreads();
    if (t == 0) last = (atomicAdd(&L3_cC, 1) == (int)gridDim.x - 1);
    __syncthreads();
    if (last) {
        __threadfence();
        for (int u = t; u < BB * 10; u += 256) {
            int b = u / 10;
            int k = u % 10;
            float cnt = fmaxf((float)g_cnti[b], 1.0f);
            float s = 0.0f;
            for (int j = 0; j < 64; j++) s += g_pool[b * 64 + j] * fcW[j * 10 + k];
            out[u] = s / cnt + fcb[k];
        }
        __syncthreads();
        for (int u = t; u < BB * 64; u += 256) g_pool[u] = 0.0f;
        if (t < BB) g_cnti[t] = 0;
        if (t == 0) { L3_cA = 0; L3_fA = 0; L3_cB = 0; L3_fB = 0; L3_cC = 0; }
        __threadfence();
    }
}

extern "C" void kernel_launch(void* const* d_in, const int* in_sizes, int n_in,
                              void* d_out, int out_size) {
    const float* x     = (const float*)d_in[0];
    const void*  ei    = d_in[1];
    const void*  batch = d_in[2];
    const float* W1 = (const float*)d_in[3];
    const float* b1 = (const float*)d_in[4];
    const float* g1 = (const float*)d_in[5];
    const float* be1 = (const float*)d_in[6];
    const float* W2 = (const float*)d_in[7];
    const float* b2 = (const float*)d_in[8];
    const float* g2 = (const float*)d_in[9];
    const float* be2 = (const float*)d_in[10];
    const float* W3 = (const float*)d_in[11];
    const float* b3 = (const float*)d_in[12];
    const float* g3 = (const float*)d_in[13];
    const float* be3 = (const float*)d_in[14];
    const float* fcW = (const float*)d_in[15];
    const float* fcb = (const float*)d_in[16];
    float* out = (float*)d_out;

    csr_kernel<<<GRID, 256>>>(ei, batch, x);
    layer1_kernel<<<391, 256>>>(W1, b1, g1, be1);
    layer2_kernel<<<GRID, 256>>>(W2, b2, g2, be2);
    layer3_kernel<<<GRID, 256>>>(W3, b3, g3, be3, fcW, fcb, out);
}

// round 16
// speedup vs baseline: 1.0402x; 1.0402x over previous
#include <cuda_runtime.h>
#include <cuda_bf16.h>

#define NN 100000
#define EE 1600000
#define BB 64
#define BNEPS 1e-5f

// g_M layout per layer: M1[din], then M2 rows padded to (din+1)
#define M1OFF 0
#define M2OFF 16
#define M3OFF 304
#define MTOT 1392

// ---------------- scratch ----------------
__device__ __align__(16) float g_P[(size_t)NN * 4];
__device__ __align__(16) __nv_bfloat16 g_Pb[(size_t)NN * 32];
__device__ __align__(16) float g_A[(size_t)NN * 32];
__device__ __align__(16) int g_degi[NN];
__device__ int g_rowptr[NN + 1];
__device__ int g_cursor[NN];
__device__ int g_src[EE];
__device__ int g_batch[NN];
__device__ float g_dis[NN];
__device__ float g_stats[128];
__device__ float g_M[MTOT];
__device__ int g_bsum[98];
__device__ int g_boff[98];
__device__ __align__(16) float g_pool[BB * 64];
__device__ int g_cnti[BB];
// sync state (all must be 0 at entry of every replay; self-resetting)
__device__ int s_cA, s_fA, s_cB, s_fB, s_fC, s_cD, s_fD, s_cF;
__device__ int l1_c, l1_f, l1_c2;
__device__ int m2_c, m2_f, m2_c2;
__device__ int m3_c, m3_f, m3_c2;

__device__ __forceinline__ int detect_e64(const void* ei) {
    const long long* p = (const long long*)ei;
    int ok = 1;
    for (int i = 0; i < 64; i++) {
        long long v = p[i];
        if (v < 0 || v >= NN) ok = 0;
    }
    return ok;
}

// block-wide arrive + wait on a global counter/flag pair
#define ARRIVE_AND_WAIT(cnt, flag) do {                                        \
    __threadfence(); __syncthreads();                                          \
    if (threadIdx.x == 0) {                                                    \
        if (atomicAdd(&(cnt), 1) == (int)gridDim.x - 1)                        \
            *((volatile int*)&(flag)) = 1;                                     \
        while (*((volatile int*)&(flag)) == 0) {}                              \
    }                                                                          \
    __syncthreads(); __threadfence();                                          \
} while (0)

// ---------------- BN solve from moments ----------------
__device__ __forceinline__ void solve_body(const float* __restrict__ W,
                                           const float* __restrict__ bias,
                                           const float* __restrict__ gam,
                                           const float* __restrict__ bet,
                                           int moff, int din, int dout, int t) {
    if (t >= dout) return;
    float m1w = 0.0f;
    for (int k = 0; k < din; k++) m1w += g_M[moff + k] * W[k * dout + t];
    float q = 0.0f;
    for (int j = 0; j < din; j++) {
        float wj = W[j * dout + t];
        const float* mrow = &g_M[moff + din + j * (din + 1)];
        for (int k = 0; k < din; k++) q += wj * mrow[k] * W[k * dout + t];
    }
    float bc = bias[t];
    const float inv_n = 1.0f / NN;
    float mu  = m1w * inv_n + bc;
    float ex2 = q * inv_n + 2.0f * bc * m1w * inv_n + bc * bc;
    float var = ex2 - mu * mu;
    float scale = gam[t] * rsqrtf(var + BNEPS);
    g_stats[t] = scale;
    g_stats[64 + t] = (bc - mu) * scale + bet[t];
}

// ---------------- persistent CSR build: hist -> scan -> fill ----------------
__global__ void __launch_bounds__(256, 4) csr_kernel(const void* ei, const void* batch,
                                                     const float* __restrict__ x) {
    int t = threadIdx.x, bid = blockIdx.x, G = gridDim.x;
    __shared__ int s64, s64b;
    __shared__ int ch[BB];
    if (t == 0) s64 = detect_e64(ei);
    if (t == 1) {
        const long long* q = (const long long*)batch;
        int okb = 1;
        for (int i2 = 0; i2 < 32; i2++) {
            long long v = q[NN / 4 + i2];
            if (v < 0 || v >= BB) okb = 0;
        }
        s64b = okb;
    }
    if (t < BB) ch[t] = 0;
    __syncthreads();
    int e64 = s64, b64 = s64b;
    for (int e = bid * 256 + t; e < EE; e += G * 256) {
        int c = e64 ? (int)((const long long*)ei)[EE + e] : ((const int*)ei)[EE + e];
        atomicAdd(&g_degi[c], 1);
    }
    for (int i = bid * 256 + t; i < NN; i += G * 256) {
        int b = b64 ? (int)((const long long*)batch)[i] : ((const int*)batch)[i];
        g_batch[i] = b;
        atomicAdd(&ch[b], 1);
    }
    __syncthreads();
    if (t < BB && ch[t]) atomicAdd(&g_cnti[t], ch[t]);
    ARRIVE_AND_WAIT(s_cA, s_fA);
    __shared__ int sh1[256];
    if (bid < 98) {
        int base = bid * 1024 + t * 4;
        int sum = 0;
        if (base + 3 < NN) {
            int4 d = *(const int4*)&g_degi[base];
            sum = d.x + d.y + d.z + d.w;
        } else {
            for (int u = 0; u < 4; u++) if (base + u < NN) sum += g_degi[base + u];
        }
        sh1[t] = sum;
        __syncthreads();
        for (int off = 128; off > 0; off >>= 1) {
            if (t < off) sh1[t] += sh1[t + off];
            __syncthreads();
        }
        if (t == 0) g_bsum[bid] = sh1[0];
    }
    ARRIVE_AND_WAIT(s_cB, s_fB);
    if (bid == 0) {
        __shared__ int s2[128];
        int v = 0;
        if (t < 128) { v = (t < 98) ? g_bsum[t] : 0; s2[t] = v; }
        __syncthreads();
        for (int off = 1; off < 128; off <<= 1) {
            int u = (t < 128 && t >= off) ? s2[t - off] : 0;
            __syncthreads();
            if (t < 128) s2[t] += u;
            __syncthreads();
        }
        if (t < 98) g_boff[t] = s2[t] - v;
        if (t == 127) g_rowptr[NN] = s2[127];
        __threadfence(); __syncthreads();
        if (t == 0) *((volatile int*)&s_fC) = 1;
    }
    if (t == 0) { while (*((volatile int*)&s_fC) == 0) {} }
    __syncthreads(); __threadfence();
    __shared__ int sh3[256];
    if (bid < 98) {
        int base = bid * 1024 + t * 4;
        int d0 = 0, d1 = 0, d2 = 0, d3 = 0;
        if (base + 3 < NN) {
            int4 d = *(const int4*)&g_degi[base];
            d0 = d.x; d1 = d.y; d2 = d.z; d3 = d.w;
            *(int4*)&g_degi[base] = make_int4(0, 0, 0, 0);
        } else {
            if (base + 0 < NN) { d0 = g_degi[base + 0]; g_degi[base + 0] = 0; }
            if (base + 1 < NN) { d1 = g_degi[base + 1]; g_degi[base + 1] = 0; }
            if (base + 2 < NN) { d2 = g_degi[base + 2]; g_degi[base + 2] = 0; }
            if (base + 3 < NN) { d3 = g_degi[base + 3]; g_degi[base + 3] = 0; }
        }
        int tsum = d0 + d1 + d2 + d3;
        sh3[t] = tsum;
        __syncthreads();
        for (int off = 1; off < 256; off <<= 1) {
            int u = (t >= off) ? sh3[t - off] : 0;
            __syncthreads();
            sh3[t] += u;
            __syncthreads();
        }
        int off = g_boff[bid] + sh3[t] - tsum;
        int pre[4] = {off, off + d0, off + d0 + d1, off + d0 + d1 + d2};
        int dd[4] = {d0, d1, d2, d3};
        for (int u = 0; u < 4; u++) {
            int idx = base + u;
            if (idx < NN) {
                g_rowptr[idx] = pre[u];
                g_cursor[idx] = pre[u];
                g_dis[idx] = rsqrtf((float)(dd[u] + 1));
            }
        }
    }
    ARRIVE_AND_WAIT(s_cD, s_fD);
    for (int e = bid * 256 + t; e < EE; e += G * 256) {
        int r, c;
        if (e64) {
            const long long* p = (const long long*)ei;
            r = (int)p[e]; c = (int)p[EE + e];
        } else {
            const int* p = (const int*)ei;
            r = p[e]; c = p[EE + e];
        }
        int pos = atomicAdd(&g_cursor[c], 1);
        g_src[pos] = r;
    }
    for (int i = bid * 256 + t; i < NN; i += G * 256) {
        float d = g_dis[i];
        ((float4*)g_P)[i] = make_float4(x[3 * i] * d, x[3 * i + 1] * d, x[3 * i + 2] * d, 0.0f);
    }
    __threadfence(); __syncthreads();
    if (t == 0) {
        if (atomicAdd(&s_cF, 1) == G - 1) {
            s_cA = 0; s_fA = 0; s_cB = 0; s_fB = 0; s_fC = 0; s_cD = 0; s_fD = 0; s_cF = 0;
            __threadfence();
        }
    }
}

// ---------------- layer 1: gather + moments + solve + fused output, one kernel ----------------
__global__ void __launch_bounds__(256, 4) layer1_kernel(const float* __restrict__ W,
                                                        const float* __restrict__ bias,
                                                        const float* __restrict__ gam,
                                                        const float* __restrict__ bet) {
    __shared__ float Wsh[48];
    __shared__ int last;
    int t = threadIdx.x;
    if (t < 48) Wsh[t] = W[t];
    int i = blockIdx.x * 256 + t;
    float4 acc = make_float4(0, 0, 0, 0);
    float d = 0.0f;
    if (i < NN) {
        const float4* __restrict__ P4 = (const float4*)g_P;
        acc = P4[i];
        int s = g_rowptr[i], e = g_rowptr[i + 1];
        int j = s;
        for (; j + 4 <= e; j += 4) {
            int r0 = g_src[j], r1 = g_src[j + 1], r2 = g_src[j + 2], r3 = g_src[j + 3];
            float4 v0 = P4[r0];
            float4 v1 = P4[r1];
            float4 v2 = P4[r2];
            float4 v3 = P4[r3];
            acc.x += (v0.x + v1.x) + (v2.x + v3.x);
            acc.y += (v0.y + v1.y) + (v2.y + v3.y);
            acc.z += (v0.z + v1.z) + (v2.z + v3.z);
            acc.w += (v0.w + v1.w) + (v2.w + v3.w);
        }
        for (; j < e; j++) {
            float4 v = P4[g_src[j]];
            acc.x += v.x; acc.y += v.y; acc.z += v.z; acc.w += v.w;
        }
        d = g_dis[i];
    }
    float s0 = acc.x * d, s1 = acc.y * d, s2 = acc.z * d;
    float m[12];
    m[0] = s0; m[1] = s1; m[2] = s2;
    m[3] = s0 * s0; m[4] = s0 * s1; m[5] = s0 * s2;
    m[6] = s1 * s0; m[7] = s1 * s1; m[8] = s1 * s2;
    m[9] = s2 * s0; m[10] = s2 * s1; m[11] = s2 * s2;
#pragma unroll
    for (int u = 0; u < 12; u++)
        for (int o = 16; o > 0; o >>= 1)
            m[u] += __shfl_down_sync(0xffffffffu, m[u], o);
    if ((t & 31) == 0) {
#pragma unroll
        for (int u = 0; u < 3; u++) atomicAdd(&g_M[M1OFF + u], m[u]);
#pragma unroll
        for (int u = 0; u < 9; u++)
            atomicAdd(&g_M[M1OFF + 3 + (u / 3) * 4 + (u % 3)], m[3 + u]);
    }
    __threadfence(); __syncthreads();
    if (t == 0) last = (atomicAdd(&l1_c, 1) == (int)gridDim.x - 1);
    __syncthreads();
    if (last) {
        solve_body(Wsh, bias, gam, bet, M1OFF, 3, 16, t);
        __syncthreads();
        if (t < 16) g_M[M1OFF + t] = 0.0f;
        __threadfence(); __syncthreads();
        if (t == 0) *((volatile int*)&l1_f) = 1;
    }
    if (t == 0) { while (*((volatile int*)&l1_f) == 0) {} }
    __syncthreads(); __threadfence();
    if (i < NN) {
        float hv[16];
#pragma unroll
        for (int c = 0; c < 16; c++) {
            float dot = acc.x * Wsh[c] + acc.y * Wsh[16 + c] + acc.z * Wsh[32 + c];
            hv[c] = fmaxf(d * dot * g_stats[c] + g_stats[64 + c], 0.0f) * d;
        }
        __nv_bfloat162 pk[8];
#pragma unroll
        for (int u = 0; u < 8; u++) pk[u] = __floats2bfloat162_rn(hv[2 * u], hv[2 * u + 1]);
        uint4* dst = (uint4*)(g_Pb + (size_t)i * 16);
        dst[0] = *(uint4*)&pk[0];
        dst[1] = *(uint4*)&pk[4];
    }
    __syncthreads();
    if (t == 0) {
        if (atomicAdd(&l1_c2, 1) == (int)gridDim.x - 1) {
            l1_c = 0; l1_c2 = 0; l1_f = 0; __threadfence();
        }
    }
}

// ---------------- bf16 gather, occupancy-tuned + index prefetch ----------------
template <int CH>
__global__ void __launch_bounds__(256, 5) gather_bf16_kernel() {
    constexpr int TPN = CH / 8;
    int idx = blockIdx.x * blockDim.x + threadIdx.x;
    if (idx >= NN * TPN) return;
    int i = idx / TPN;
    int sub = idx % TPN;
    const uint4* __restrict__ Pb = (const uint4*)g_Pb;
    float acc[8];
    {
        uint4 v = Pb[(size_t)i * TPN + sub];
        const __nv_bfloat162* h = (const __nv_bfloat162*)&v;
#pragma unroll
        for (int u = 0; u < 4; u++) {
            float2 f = __bfloat1622float2(h[u]);
            acc[2 * u] = f.x; acc[2 * u + 1] = f.y;
        }
    }
    int s = g_rowptr[i], e = g_rowptr[i + 1];
    int j = s;
    int r0, r1, r2, r3;
    bool have = (j + 4 <= e);
    if (have) { r0 = g_src[j]; r1 = g_src[j + 1]; r2 = g_src[j + 2]; r3 = g_src[j + 3]; }
    while (have) {
        uint4 v0 = Pb[(size_t)r0 * TPN + sub];
        uint4 v1 = Pb[(size_t)r1 * TPN + sub];
        uint4 v2 = Pb[(size_t)r2 * TPN + sub];
        uint4 v3 = Pb[(size_t)r3 * TPN + sub];
        j += 4;
        have = (j + 4 <= e);
        if (have) {  // prefetch next indices before consuming features
            r0 = g_src[j]; r1 = g_src[j + 1]; r2 = g_src[j + 2]; r3 = g_src[j + 3];
        }
        const __nv_bfloat162* h0 = (const __nv_bfloat162*)&v0;
        const __nv_bfloat162* h1 = (const __nv_bfloat162*)&v1;
        const __nv_bfloat162* h2 = (const __nv_bfloat162*)&v2;
        const __nv_bfloat162* h3 = (const __nv_bfloat162*)&v3;
#pragma unroll
        for (int u = 0; u < 4; u++) {
            float2 f0 = __bfloat1622float2(h0[u]);
            float2 f1 = __bfloat1622float2(h1[u]);
            float2 f2 = __bfloat1622float2(h2[u]);
            float2 f3 = __bfloat1622float2(h3[u]);
            acc[2 * u]     += (f0.x + f1.x) + (f2.x + f3.x);
            acc[2 * u + 1] += (f0.y + f1.y) + (f2.y + f3.y);
        }
    }
    for (; j < e; j++) {
        uint4 v = Pb[(size_t)g_src[j] * TPN + sub];
        const __nv_bfloat162* h = (const __nv_bfloat162*)&v;
#pragma unroll
        for (int u = 0; u < 4; u++) {
            float2 f = __bfloat1622float2(h[u]);
            acc[2 * u] += f.x; acc[2 * u + 1] += f.y;
        }
    }
    float4* Ao = (float4*)(g_A + (size_t)i * CH + sub * 8);
    Ao[0] = make_float4(acc[0], acc[1], acc[2], acc[3]);
    Ao[1] = make_float4(acc[4], acc[5], acc[6], acc[7]);
}

// ---------------- moments phase (device helper) ----------------
template <int DIN, int MOFF>
__device__ __forceinline__ void mom_phase(int t) {
    constexpr int RPW = 32 / DIN;
    constexpr int NIT = DIN + DIN * (DIN + 1);
    __shared__ float Msh[NIT];
    for (int u = t; u < NIT; u += 256) Msh[u] = 0.0f;
    __syncthreads();
    int lane = t & 31, w = t >> 5;
    int gw = blockIdx.x * 8 + w;
    int sub = lane / DIN;
    int ch = lane % DIN;
    float acc1 = 0.0f;
    float acc2[DIN];
#pragma unroll
    for (int k = 0; k < DIN; k++) acc2[k] = 0.0f;
    int stride = gridDim.x * 8 * RPW;
    for (int r0 = gw * RPW; r0 < NN; r0 += stride) {
        int r = r0 + sub;
        float s = g_A[(size_t)r * DIN + ch] * g_dis[r];
        acc1 += s;
#pragma unroll
        for (int k = 0; k < DIN; k++)
            acc2[k] += s * __shfl_sync(0xffffffffu, s, k, DIN);
    }
    atomicAdd(&Msh[ch], acc1);
#pragma unroll
    for (int k = 0; k < DIN; k++)
        atomicAdd(&Msh[DIN + ch * (DIN + 1) + k], acc2[k]);
    __syncthreads();
    for (int u = t; u < NIT; u += 256) atomicAdd(&g_M[MOFF + u], Msh[u]);
}

// ---------------- layer 2: moments + solve + fused output ----------------
__global__ void __launch_bounds__(256, 4) momfused2_kernel(const float* __restrict__ W,
                                                           const float* __restrict__ bias,
                                                           const float* __restrict__ gam,
                                                           const float* __restrict__ bet) {
    __shared__ float Wsh[16 * 32];
    __shared__ int last;
    int t = threadIdx.x;
    for (int u = t; u < 512; u += 256) Wsh[u] = W[u];
    mom_phase<16, M2OFF>(t);
    __threadfence(); __syncthreads();
    if (t == 0) last = (atomicAdd(&m2_c, 1) == (int)gridDim.x - 1);
    __syncthreads();
    if (last) {
        solve_body(Wsh, bias, gam, bet, M2OFF, 16, 32, t);
        __syncthreads();
        for (int u = t; u < 288; u += 256) g_M[M2OFF + u] = 0.0f;
        __threadfence(); __syncthreads();
        if (t == 0) *((volatile int*)&m2_f) = 1;
    }
    if (t == 0) { while (*((volatile int*)&m2_f) == 0) {} }
    __syncthreads(); __threadfence();
    int c = t & 31;
    float scale = g_stats[c], off = g_stats[64 + c];
    int rstart = blockIdx.x * 8 + (t >> 5);
    int rstride = gridDim.x * 8;
    for (int i = rstart; i < NN; i += rstride) {
        const float4* a4 = (const float4*)(g_A + (size_t)i * 16);
        float dot = 0.0f;
#pragma unroll
        for (int kk = 0; kk < 4; kk++) {
            float4 av = a4[kk];
            int kb = kk * 4;
            dot += av.x * Wsh[(kb + 0) * 32 + c];
            dot += av.y * Wsh[(kb + 1) * 32 + c];
            dot += av.z * Wsh[(kb + 2) * 32 + c];
            dot += av.w * Wsh[(kb + 3) * 32 + c];
        }
        float d = g_dis[i];
        float h = fmaxf(d * dot * scale + off, 0.0f);
        g_Pb[(size_t)i * 32 + c] = __float2bfloat16(h * d);
    }
    __syncthreads();
    if (t == 0) {
        if (atomicAdd(&m2_c2, 1) == (int)gridDim.x - 1) {
            m2_c = 0; m2_c2 = 0; m2_f = 0; __threadfence();
        }
    }
}

// ---------------- layer 3: moments + solve + fused bn/relu -> pool -> FC ----------------
__global__ void __launch_bounds__(256, 4) momfused3_kernel(const float* __restrict__ W,
                                                           const float* __restrict__ bias,
                                                           const float* __restrict__ gam,
                                                           const float* __restrict__ bet,
                                                           const float* __restrict__ fcW,
                                                           const float* __restrict__ fcb,
                                                           float* __restrict__ out) {
    __shared__ float Wsh[32 * 64];
    __shared__ float pool[BB * 64];
    __shared__ int last;
    int t = threadIdx.x;
    for (int u = t; u < 2048; u += 256) Wsh[u] = W[u];
    for (int u = t; u < BB * 64; u += 256) pool[u] = 0.0f;
    mom_phase<32, M3OFF>(t);
    __threadfence(); __syncthreads();
    if (t == 0) last = (atomicAdd(&m3_c, 1) == (int)gridDim.x - 1);
    __syncthreads();
    if (last) {
        solve_body(Wsh, bias, gam, bet, M3OFF, 32, 64, t);
        __syncthreads();
        for (int u = t; u < 1088; u += 256) g_M[M3OFF + u] = 0.0f;
        __threadfence(); __syncthreads();
        if (t == 0) *((volatile int*)&m3_f) = 1;
    }
    if (t == 0) { while (*((volatile int*)&m3_f) == 0) {} }
    __syncthreads(); __threadfence();
    int c = t & 63;
    float scale = g_stats[c], off = g_stats[64 + c];
    int rstart = blockIdx.x * 4 + (t >> 6);
    int rstride = gridDim.x * 4;
    for (int i = rstart; i < NN; i += rstride) {
        const float4* a4 = (const float4*)(g_A + (size_t)i * 32);
        float dot = 0.0f;
#pragma unroll
        for (int kk = 0; kk < 8; kk++) {
            float4 av = a4[kk];
            int kb = kk * 4;
            dot += av.x * Wsh[(kb + 0) * 64 + c];
            dot += av.y * Wsh[(kb + 1) * 64 + c];
            dot += av.z * Wsh[(kb + 2) * 64 + c];
            dot += av.w * Wsh[(kb + 3) * 64 + c];
        }
        float d = g_dis[i];
        float h = fmaxf(d * dot * scale + off, 0.0f);
        atomicAdd(&pool[g_batch[i] * 64 + c], h);
    }
    __syncthreads();
    for (int u = t; u < BB * 16; u += 256) {
        float4 v = ((const float4*)pool)[u];
        float* dst = g_pool + u * 4;
        unsigned long long p = (unsigned long long)__cvta_generic_to_global(dst);
        asm volatile("red.global.add.v4.f32 [%0], {%1,%2,%3,%4};"
                     :: "l"(p), "f"(v.x), "f"(v.y), "f"(v.z), "f"(v.w) : "memory");
    }
    __threadfence(); __syncthreads();
    if (t == 0) last = (atomicAdd(&m3_c2, 1) == (int)gridDim.x - 1);
    __syncthreads();
    if (last) {
        __threadfence();
        for (int u = t; u < BB * 10; u += 256) {
            int b = u / 10;
            int k = u % 10;
            float cnt = fmaxf((float)g_cnti[b], 1.0f);
            float s = 0.0f;
            for (int j = 0; j < 64; j++) s += g_pool[b * 64 + j] * fcW[j * 10 + k];
            out[u] = s / cnt + fcb[k];
        }
        __syncthreads();
        for (int u = t; u < BB * 64; u += 256) g_pool[u] = 0.0f;
        if (t < BB) g_cnti[t] = 0;
        if (t == 0) { m3_c = 0; m3_c2 = 0; m3_f = 0; }
        __threadfence();
    }
}

extern "C" void kernel_launch(void* const* d_in, const int* in_sizes, int n_in,
                              void* d_out, int out_size) {
    const float* x     = (const float*)d_in[0];
    const void*  ei    = d_in[1];
    const void*  batch = d_in[2];
    const float* W1 = (const float*)d_in[3];
    const float* b1 = (const float*)d_in[4];
    const float* g1 = (const float*)d_in[5];
    const float* be1 = (const float*)d_in[6];
    const float* W2 = (const float*)d_in[7];
    const float* b2 = (const float*)d_in[8];
    const float* g2 = (const float*)d_in[9];
    const float* be2 = (const float*)d_in[10];
    const float* W3 = (const float*)d_in[11];
    const float* b3 = (const float*)d_in[12];
    const float* g3 = (const float*)d_in[13];
    const float* be3 = (const float*)d_in[14];
    const float* fcW = (const float*)d_in[15];
    const float* fcb = (const float*)d_in[16];
    float* out = (float*)d_out;

    csr_kernel<<<592, 256>>>(ei, batch, x);
    layer1_kernel<<<391, 256>>>(W1, b1, g1, be1);
    gather_bf16_kernel<16><<<(NN * 2 + 255) / 256, 256>>>();
    momfused2_kernel<<<592, 256>>>(W2, b2, g2, be2);
    gather_bf16_kernel<32><<<(NN * 4 + 255) / 256, 256>>>();
    momfused3_kernel<<<592, 256>>>(W3, b3, g3, be3, fcW, fcb, out);
}

// round 17
// speedup vs baseline: 1.1460x; 1.1018x over previous
#include <cuda_runtime.h>
#include <cuda_bf16.h>

#define NN 100000
#define EE 1600000
#define BB 64
#define BNEPS 1e-5f

// g_M layout per layer: M1[din], then M2 rows padded to (din+1)
#define M1OFF 0
#define M2OFF 16
#define M3OFF 304
#define MTOT 1392

// ---------------- scratch ----------------
__device__ __align__(16) float g_P[(size_t)NN * 4];
__device__ __align__(16) __nv_bfloat16 g_Pb[(size_t)NN * 32];
__device__ __align__(16) __nv_bfloat16 g_Ab[(size_t)NN * 32];   // bf16 aggregation result
__device__ __align__(16) int g_degi[NN];
__device__ int g_rowptr[NN + 1];
__device__ int g_cursor[NN];
__device__ int g_src[EE];
__device__ int g_batch[NN];
__device__ float g_dis[NN];
__device__ float g_stats[128];
__device__ float g_M[MTOT];
__device__ int g_bsum[98];
__device__ int g_boff[98];
__device__ __align__(16) float g_pool[BB * 64];
__device__ int g_cnti[BB];
// sync state (all must be 0 at entry of every replay; self-resetting)
__device__ int s_cA, s_fA, s_cB, s_fB, s_fC, s_cD, s_fD, s_cF;
__device__ int l1_c, l1_f, l1_c2;
__device__ int m2_c, m2_f, m2_c2;
__device__ int m3_c, m3_f, m3_c2;

__device__ __forceinline__ int detect_e64(const void* ei) {
    const long long* p = (const long long*)ei;
    int ok = 1;
    for (int i = 0; i < 64; i++) {
        long long v = p[i];
        if (v < 0 || v >= NN) ok = 0;
    }
    return ok;
}

// block-wide arrive + wait on a global counter/flag pair
#define ARRIVE_AND_WAIT(cnt, flag) do {                                        \
    __threadfence(); __syncthreads();                                          \
    if (threadIdx.x == 0) {                                                    \
        if (atomicAdd(&(cnt), 1) == (int)gridDim.x - 1)                        \
            *((volatile int*)&(flag)) = 1;                                     \
        while (*((volatile int*)&(flag)) == 0) {}                              \
    }                                                                          \
    __syncthreads(); __threadfence();                                          \
} while (0)

// ---------------- BN solve from moments (small-din serial variant, layer 1) ----------------
__device__ __forceinline__ void solve_body(const float* __restrict__ W,
                                           const float* __restrict__ bias,
                                           const float* __restrict__ gam,
                                           const float* __restrict__ bet,
                                           int moff, int din, int dout, int t) {
    if (t >= dout) return;
    float m1w = 0.0f;
    for (int k = 0; k < din; k++) m1w += g_M[moff + k] * W[k * dout + t];
    float q = 0.0f;
    for (int j = 0; j < din; j++) {
        float wj = W[j * dout + t];
        const float* mrow = &g_M[moff + din + j * (din + 1)];
        for (int k = 0; k < din; k++) q += wj * mrow[k] * W[k * dout + t];
    }
    float bc = bias[t];
    const float inv_n = 1.0f / NN;
    float mu  = m1w * inv_n + bc;
    float ex2 = q * inv_n + 2.0f * bc * m1w * inv_n + bc * bc;
    float var = ex2 - mu * mu;
    float scale = gam[t] * rsqrtf(var + BNEPS);
    g_stats[t] = scale;
    g_stats[64 + t] = (bc - mu) * scale + bet[t];
}

// ---------------- fast parallel BN solve from smem-staged moments ----------------
template <int DIN, int DOUT>
__device__ __forceinline__ void solve_fast(const float* __restrict__ Wsh,
                                           const float* __restrict__ bias,
                                           const float* __restrict__ gam,
                                           const float* __restrict__ bet,
                                           const float* __restrict__ Msh,
                                           float* __restrict__ qsh, int t) {
    constexpr int NP = 256 / DOUT;
    int c = t % DOUT;
    int part = t / DOUT;
    if (t < DOUT) qsh[t] = 0.0f;
    __syncthreads();
    float q = 0.0f;
    for (int j = part; j < DIN; j += NP) {
        float wj = Wsh[j * DOUT + c];
        const float* mrow = &Msh[DIN + j * (DIN + 1)];
        float a = 0.0f;
#pragma unroll
        for (int k = 0; k < DIN; k++) a += mrow[k] * Wsh[k * DOUT + c];
        q += wj * a;
    }
    atomicAdd(&qsh[c], q);
    __syncthreads();
    if (t < DOUT) {
        float m1w = 0.0f;
#pragma unroll
        for (int k = 0; k < DIN; k++) m1w += Msh[k] * Wsh[k * DOUT + t];
        float bc = bias[t];
        const float inv_n = 1.0f / NN;
        float mu  = m1w * inv_n + bc;
        float ex2 = qsh[t] * inv_n + 2.0f * bc * m1w * inv_n + bc * bc;
        float var = ex2 - mu * mu;
        float scale = gam[t] * rsqrtf(var + BNEPS);
        g_stats[t] = scale;
        g_stats[64 + t] = (bc - mu) * scale + bet[t];
    }
}

// ---------------- persistent CSR build: hist -> scan -> fill ----------------
__global__ void __launch_bounds__(256, 4) csr_kernel(const void* ei, const void* batch,
                                                     const float* __restrict__ x) {
    int t = threadIdx.x, bid = blockIdx.x, G = gridDim.x;
    __shared__ int s64, s64b;
    __shared__ int ch[BB];
    if (t == 0) s64 = detect_e64(ei);
    if (t == 1) {
        const long long* q = (const long long*)batch;
        int okb = 1;
        for (int i2 = 0; i2 < 32; i2++) {
            long long v = q[NN / 4 + i2];
            if (v < 0 || v >= BB) okb = 0;
        }
        s64b = okb;
    }
    if (t < BB) ch[t] = 0;
    __syncthreads();
    int e64 = s64, b64 = s64b;
    for (int e = bid * 256 + t; e < EE; e += G * 256) {
        int c = e64 ? (int)((const long long*)ei)[EE + e] : ((const int*)ei)[EE + e];
        atomicAdd(&g_degi[c], 1);
    }
    for (int i = bid * 256 + t; i < NN; i += G * 256) {
        int b = b64 ? (int)((const long long*)batch)[i] : ((const int*)batch)[i];
        g_batch[i] = b;
        atomicAdd(&ch[b], 1);
    }
    __syncthreads();
    if (t < BB && ch[t]) atomicAdd(&g_cnti[t], ch[t]);
    ARRIVE_AND_WAIT(s_cA, s_fA);
    __shared__ int sh1[256];
    if (bid < 98) {
        int base = bid * 1024 + t * 4;
        int sum = 0;
        if (base + 3 < NN) {
            int4 d = *(const int4*)&g_degi[base];
            sum = d.x + d.y + d.z + d.w;
        } else {
            for (int u = 0; u < 4; u++) if (base + u < NN) sum += g_degi[base + u];
        }
        sh1[t] = sum;
        __syncthreads();
        for (int off = 128; off > 0; off >>= 1) {
            if (t < off) sh1[t] += sh1[t + off];
            __syncthreads();
        }
        if (t == 0) g_bsum[bid] = sh1[0];
    }
    ARRIVE_AND_WAIT(s_cB, s_fB);
    if (bid == 0) {
        __shared__ int s2[128];
        int v = 0;
        if (t < 128) { v = (t < 98) ? g_bsum[t] : 0; s2[t] = v; }
        __syncthreads();
        for (int off = 1; off < 128; off <<= 1) {
            int u = (t < 128 && t >= off) ? s2[t - off] : 0;
            __syncthreads();
            if (t < 128) s2[t] += u;
            __syncthreads();
        }
        if (t < 98) g_boff[t] = s2[t] - v;
        if (t == 127) g_rowptr[NN] = s2[127];
        __threadfence(); __syncthreads();
        if (t == 0) *((volatile int*)&s_fC) = 1;
    }
    if (t == 0) { while (*((volatile int*)&s_fC) == 0) {} }
    __syncthreads(); __threadfence();
    __shared__ int sh3[256];
    if (bid < 98) {
        int base = bid * 1024 + t * 4;
        int d0 = 0, d1 = 0, d2 = 0, d3 = 0;
        if (base + 3 < NN) {
            int4 d = *(const int4*)&g_degi[base];
            d0 = d.x; d1 = d.y; d2 = d.z; d3 = d.w;
            *(int4*)&g_degi[base] = make_int4(0, 0, 0, 0);
        } else {
            if (base + 0 < NN) { d0 = g_degi[base + 0]; g_degi[base + 0] = 0; }
            if (base + 1 < NN) { d1 = g_degi[base + 1]; g_degi[base + 1] = 0; }
            if (base + 2 < NN) { d2 = g_degi[base + 2]; g_degi[base + 2] = 0; }
            if (base + 3 < NN) { d3 = g_degi[base + 3]; g_degi[base + 3] = 0; }
        }
        int tsum = d0 + d1 + d2 + d3;
        sh3[t] = tsum;
        __syncthreads();
        for (int off = 1; off < 256; off <<= 1) {
            int u = (t >= off) ? sh3[t - off] : 0;
            __syncthreads();
            sh3[t] += u;
            __syncthreads();
        }
        int off = g_boff[bid] + sh3[t] - tsum;
        int pre[4] = {off, off + d0, off + d0 + d1, off + d0 + d1 + d2};
        int dd[4] = {d0, d1, d2, d3};
        for (int u = 0; u < 4; u++) {
            int idx = base + u;
            if (idx < NN) {
                g_rowptr[idx] = pre[u];
                g_cursor[idx] = pre[u];
                g_dis[idx] = rsqrtf((float)(dd[u] + 1));
            }
        }
    }
    ARRIVE_AND_WAIT(s_cD, s_fD);
    for (int e = bid * 256 + t; e < EE; e += G * 256) {
        int r, c;
        if (e64) {
            const long long* p = (const long long*)ei;
            r = (int)p[e]; c = (int)p[EE + e];
        } else {
            const int* p = (const int*)ei;
            r = p[e]; c = p[EE + e];
        }
        int pos = atomicAdd(&g_cursor[c], 1);
        g_src[pos] = r;
    }
    for (int i = bid * 256 + t; i < NN; i += G * 256) {
        float d = g_dis[i];
        ((float4*)g_P)[i] = make_float4(x[3 * i] * d, x[3 * i + 1] * d, x[3 * i + 2] * d, 0.0f);
    }
    __threadfence(); __syncthreads();
    if (t == 0) {
        if (atomicAdd(&s_cF, 1) == G - 1) {
            s_cA = 0; s_fA = 0; s_cB = 0; s_fB = 0; s_fC = 0; s_cD = 0; s_fD = 0; s_cF = 0;
            __threadfence();
        }
    }
}

// ---------------- layer 1: gather + moments + solve + fused output, one kernel ----------------
__global__ void __launch_bounds__(256, 4) layer1_kernel(const float* __restrict__ W,
                                                        const float* __restrict__ bias,
                                                        const float* __restrict__ gam,
                                                        const float* __restrict__ bet) {
    __shared__ float Wsh[48];
    __shared__ int last;
    int t = threadIdx.x;
    if (t < 48) Wsh[t] = W[t];
    int i = blockIdx.x * 256 + t;
    float4 acc = make_float4(0, 0, 0, 0);
    float d = 0.0f;
    if (i < NN) {
        const float4* __restrict__ P4 = (const float4*)g_P;
        acc = P4[i];
        int s = g_rowptr[i], e = g_rowptr[i + 1];
        int j = s;
        for (; j + 4 <= e; j += 4) {
            int r0 = g_src[j], r1 = g_src[j + 1], r2 = g_src[j + 2], r3 = g_src[j + 3];
            float4 v0 = P4[r0];
            float4 v1 = P4[r1];
            float4 v2 = P4[r2];
            float4 v3 = P4[r3];
            acc.x += (v0.x + v1.x) + (v2.x + v3.x);
            acc.y += (v0.y + v1.y) + (v2.y + v3.y);
            acc.z += (v0.z + v1.z) + (v2.z + v3.z);
            acc.w += (v0.w + v1.w) + (v2.w + v3.w);
        }
        for (; j < e; j++) {
            float4 v = P4[g_src[j]];
            acc.x += v.x; acc.y += v.y; acc.z += v.z; acc.w += v.w;
        }
        d = g_dis[i];
    }
    float s0 = acc.x * d, s1 = acc.y * d, s2 = acc.z * d;
    float m[12];
    m[0] = s0; m[1] = s1; m[2] = s2;
    m[3] = s0 * s0; m[4] = s0 * s1; m[5] = s0 * s2;
    m[6] = s1 * s0; m[7] = s1 * s1; m[8] = s1 * s2;
    m[9] = s2 * s0; m[10] = s2 * s1; m[11] = s2 * s2;
#pragma unroll
    for (int u = 0; u < 12; u++)
        for (int o = 16; o > 0; o >>= 1)
            m[u] += __shfl_down_sync(0xffffffffu, m[u], o);
    if ((t & 31) == 0) {
#pragma unroll
        for (int u = 0; u < 3; u++) atomicAdd(&g_M[M1OFF + u], m[u]);
#pragma unroll
        for (int u = 0; u < 9; u++)
            atomicAdd(&g_M[M1OFF + 3 + (u / 3) * 4 + (u % 3)], m[3 + u]);
    }
    __threadfence(); __syncthreads();
    if (t == 0) last = (atomicAdd(&l1_c, 1) == (int)gridDim.x - 1);
    __syncthreads();
    if (last) {
        solve_body(Wsh, bias, gam, bet, M1OFF, 3, 16, t);
        __syncthreads();
        if (t < 16) g_M[M1OFF + t] = 0.0f;
        __threadfence(); __syncthreads();
        if (t == 0) *((volatile int*)&l1_f) = 1;
    }
    if (t == 0) { while (*((volatile int*)&l1_f) == 0) {} }
    __syncthreads(); __threadfence();
    if (i < NN) {
        float hv[16];
#pragma unroll
        for (int c = 0; c < 16; c++) {
            float dot = acc.x * Wsh[c] + acc.y * Wsh[16 + c] + acc.z * Wsh[32 + c];
            hv[c] = fmaxf(d * dot * g_stats[c] + g_stats[64 + c], 0.0f) * d;
        }
        __nv_bfloat162 pk[8];
#pragma unroll
        for (int u = 0; u < 8; u++) pk[u] = __floats2bfloat162_rn(hv[2 * u], hv[2 * u + 1]);
        uint4* dst = (uint4*)(g_Pb + (size_t)i * 16);
        dst[0] = *(uint4*)&pk[0];
        dst[1] = *(uint4*)&pk[4];
    }
    __syncthreads();
    if (t == 0) {
        if (atomicAdd(&l1_c2, 1) == (int)gridDim.x - 1) {
            l1_c = 0; l1_c2 = 0; l1_f = 0; __threadfence();
        }
    }
}

// ---------------- bf16 gather, index prefetch; writes bf16 A ----------------
template <int CH>
__global__ void __launch_bounds__(256, 5) gather_bf16_kernel() {
    constexpr int TPN = CH / 8;
    int idx = blockIdx.x * blockDim.x + threadIdx.x;
    if (idx >= NN * TPN) return;
    int i = idx / TPN;
    int sub = idx % TPN;
    const uint4* __restrict__ Pb = (const uint4*)g_Pb;
    float acc[8];
    {
        uint4 v = Pb[(size_t)i * TPN + sub];
        const __nv_bfloat162* h = (const __nv_bfloat162*)&v;
#pragma unroll
        for (int u = 0; u < 4; u++) {
            float2 f = __bfloat1622float2(h[u]);
            acc[2 * u] = f.x; acc[2 * u + 1] = f.y;
        }
    }
    int s = g_rowptr[i], e = g_rowptr[i + 1];
    int j = s;
    int r0, r1, r2, r3;
    bool have = (j + 4 <= e);
    if (have) { r0 = g_src[j]; r1 = g_src[j + 1]; r2 = g_src[j + 2]; r3 = g_src[j + 3]; }
    while (have) {
        uint4 v0 = Pb[(size_t)r0 * TPN + sub];
        uint4 v1 = Pb[(size_t)r1 * TPN + sub];
        uint4 v2 = Pb[(size_t)r2 * TPN + sub];
        uint4 v3 = Pb[(size_t)r3 * TPN + sub];
        j += 4;
        have = (j + 4 <= e);
        if (have) {
            r0 = g_src[j]; r1 = g_src[j + 1]; r2 = g_src[j + 2]; r3 = g_src[j + 3];
        }
        const __nv_bfloat162* h0 = (const __nv_bfloat162*)&v0;
        const __nv_bfloat162* h1 = (const __nv_bfloat162*)&v1;
        const __nv_bfloat162* h2 = (const __nv_bfloat162*)&v2;
        const __nv_bfloat162* h3 = (const __nv_bfloat162*)&v3;
#pragma unroll
        for (int u = 0; u < 4; u++) {
            float2 f0 = __bfloat1622float2(h0[u]);
            float2 f1 = __bfloat1622float2(h1[u]);
            float2 f2 = __bfloat1622float2(h2[u]);
            float2 f3 = __bfloat1622float2(h3[u]);
            acc[2 * u]     += (f0.x + f1.x) + (f2.x + f3.x);
            acc[2 * u + 1] += (f0.y + f1.y) + (f2.y + f3.y);
        }
    }
    for (; j < e; j++) {
        uint4 v = Pb[(size_t)g_src[j] * TPN + sub];
        const __nv_bfloat162* h = (const __nv_bfloat162*)&v;
#pragma unroll
        for (int u = 0; u < 4; u++) {
            float2 f = __bfloat1622float2(h[u]);
            acc[2 * u] += f.x; acc[2 * u + 1] += f.y;
        }
    }
    // write bf16 A (8 values = 16B)
    __nv_bfloat162 o[4];
#pragma unroll
    for (int u = 0; u < 4; u++) o[u] = __floats2bfloat162_rn(acc[2 * u], acc[2 * u + 1]);
    *(uint4*)(g_Ab + (size_t)i * CH + sub * 8) = *(uint4*)&o[0];
}

// ---------------- moments phase (bf16 A) ----------------
template <int DIN, int MOFF>
__device__ __forceinline__ void mom_phase(int t) {
    constexpr int RPW = 32 / DIN;
    constexpr int NIT = DIN + DIN * (DIN + 1);
    __shared__ float Msh[NIT];
    for (int u = t; u < NIT; u += 256) Msh[u] = 0.0f;
    __syncthreads();
    int lane = t & 31, w = t >> 5;
    int gw = blockIdx.x * 8 + w;
    int sub = lane / DIN;
    int ch = lane % DIN;
    float acc1 = 0.0f;
    float acc2[DIN];
#pragma unroll
    for (int k = 0; k < DIN; k++) acc2[k] = 0.0f;
    int stride = gridDim.x * 8 * RPW;
    for (int r0 = gw * RPW; r0 < NN; r0 += stride) {
        int r = r0 + sub;
        float s = __bfloat162float(g_Ab[(size_t)r * DIN + ch]) * g_dis[r];
        acc1 += s;
#pragma unroll
        for (int k = 0; k < DIN; k++)
            acc2[k] += s * __shfl_sync(0xffffffffu, s, k, DIN);
    }
    atomicAdd(&Msh[ch], acc1);
#pragma unroll
    for (int k = 0; k < DIN; k++)
        atomicAdd(&Msh[DIN + ch * (DIN + 1) + k], acc2[k]);
    __syncthreads();
    for (int u = t; u < NIT; u += 256) atomicAdd(&g_M[MOFF + u], Msh[u]);
}

// ---------------- layer 2: moments + fast solve + fused output ----------------
__global__ void __launch_bounds__(256, 4) momfused2_kernel(const float* __restrict__ W,
                                                           const float* __restrict__ bias,
                                                           const float* __restrict__ gam,
                                                           const float* __restrict__ bet) {
    __shared__ float Wsh[16 * 32];
    __shared__ float MshS[288];
    __shared__ float qsh[64];
    __shared__ int last;
    int t = threadIdx.x;
    for (int u = t; u < 512; u += 256) Wsh[u] = W[u];
    mom_phase<16, M2OFF>(t);
    __threadfence(); __syncthreads();
    if (t == 0) last = (atomicAdd(&m2_c, 1) == (int)gridDim.x - 1);
    __syncthreads();
    if (last) {
        for (int u = t; u < 288; u += 256) MshS[u] = g_M[M2OFF + u];
        __syncthreads();
        for (int u = t; u < 288; u += 256) g_M[M2OFF + u] = 0.0f;
        solve_fast<16, 32>(Wsh, bias, gam, bet, MshS, qsh, t);
        __threadfence(); __syncthreads();
        if (t == 0) *((volatile int*)&m2_f) = 1;
    }
    if (t == 0) { while (*((volatile int*)&m2_f) == 0) {} }
    __syncthreads(); __threadfence();
    int c = t & 31;
    float scale = g_stats[c], off = g_stats[64 + c];
    int rstart = blockIdx.x * 8 + (t >> 5);
    int rstride = gridDim.x * 8;
    for (int i = rstart; i < NN; i += rstride) {
        const uint4* a4 = (const uint4*)(g_Ab + (size_t)i * 16);
        uint4 p0 = a4[0], p1 = a4[1];
        const __nv_bfloat162* h0 = (const __nv_bfloat162*)&p0;
        const __nv_bfloat162* h1 = (const __nv_bfloat162*)&p1;
        float dot = 0.0f;
#pragma unroll
        for (int u = 0; u < 4; u++) {
            float2 f = __bfloat1622float2(h0[u]);
            dot += f.x * Wsh[(2 * u) * 32 + c] + f.y * Wsh[(2 * u + 1) * 32 + c];
        }
#pragma unroll
        for (int u = 0; u < 4; u++) {
            float2 f = __bfloat1622float2(h1[u]);
            dot += f.x * Wsh[(8 + 2 * u) * 32 + c] + f.y * Wsh[(9 + 2 * u) * 32 + c];
        }
        float d = g_dis[i];
        float h = fmaxf(d * dot * scale + off, 0.0f);
        g_Pb[(size_t)i * 32 + c] = __float2bfloat16(h * d);
    }
    __syncthreads();
    if (t == 0) {
        if (atomicAdd(&m2_c2, 1) == (int)gridDim.x - 1) {
            m2_c = 0; m2_c2 = 0; m2_f = 0; __threadfence();
        }
    }
}

// ---------------- layer 3: moments + fast solve + fused bn/relu -> pool -> FC ----------------
__global__ void __launch_bounds__(256, 4) momfused3_kernel(const float* __restrict__ W,
                                                           const float* __restrict__ bias,
                                                           const float* __restrict__ gam,
                                                           const float* __restrict__ bet,
                                                           const float* __restrict__ fcW,
                                                           const float* __restrict__ fcb,
                                                           float* __restrict__ out) {
    __shared__ float Wsh[32 * 64];
    __shared__ float pool[BB * 64];
    __shared__ float MshS[1088];
    __shared__ float qsh[64];
    __shared__ int last;
    int t = threadIdx.x;
    for (int u = t; u < 2048; u += 256) Wsh[u] = W[u];
    for (int u = t; u < BB * 64; u += 256) pool[u] = 0.0f;
    mom_phase<32, M3OFF>(t);
    __threadfence(); __syncthreads();
    if (t == 0) last = (atomicAdd(&m3_c, 1) == (int)gridDim.x - 1);
    __syncthreads();
    if (last) {
        for (int u = t; u < 1088; u += 256) MshS[u] = g_M[M3OFF + u];
        __syncthreads();
        for (int u = t; u < 1088; u += 256) g_M[M3OFF + u] = 0.0f;
        solve_fast<32, 64>(Wsh, bias, gam, bet, MshS, qsh, t);
        __threadfence(); __syncthreads();
        if (t == 0) *((volatile int*)&m3_f) = 1;
    }
    if (t == 0) { while (*((volatile int*)&m3_f) == 0) {} }
    __syncthreads(); __threadfence();
    int c = t & 63;
    float scale = g_stats[c], off = g_stats[64 + c];
    int rstart = blockIdx.x * 4 + (t >> 6);
    int rstride = gridDim.x * 4;
    for (int i = rstart; i < NN; i += rstride) {
        const uint4* a4 = (const uint4*)(g_Ab + (size_t)i * 32);
        float dot = 0.0f;
#pragma unroll
        for (int g = 0; g < 4; g++) {
            uint4 p = a4[g];
            const __nv_bfloat162* h = (const __nv_bfloat162*)&p;
#pragma unroll
            for (int u = 0; u < 4; u++) {
                float2 f = __bfloat1622float2(h[u]);
                int kb = g * 8 + 2 * u;
                dot += f.x * Wsh[kb * 64 + c] + f.y * Wsh[(kb + 1) * 64 + c];
            }
        }
        float d = g_dis[i];
        float h = fmaxf(d * dot * scale + off, 0.0f);
        atomicAdd(&pool[g_batch[i] * 64 + c], h);
    }
    __syncthreads();
    for (int u = t; u < BB * 16; u += 256) {
        float4 v = ((const float4*)pool)[u];
        float* dst = g_pool + u * 4;
        unsigned long long p = (unsigned long long)__cvta_generic_to_global(dst);
        asm volatile("red.global.add.v4.f32 [%0], {%1,%2,%3,%4};"
                     :: "l"(p), "f"(v.x), "f"(v.y), "f"(v.z), "f"(v.w) : "memory");
    }
    __threadfence(); __syncthreads();
    if (t == 0) last = (atomicAdd(&m3_c2, 1) == (int)gridDim.x - 1);
    __syncthreads();
    if (last) {
        __threadfence();
        for (int u = t; u < BB * 10; u += 256) {
            int b = u / 10;
            int k = u % 10;
            float cnt = fmaxf((float)g_cnti[b], 1.0f);
            float s = 0.0f;
            for (int j = 0; j < 64; j++) s += g_pool[b * 64 + j] * fcW[j * 10 + k];
            out[u] = s / cnt + fcb[k];
        }
        __syncthreads();
        for (int u = t; u < BB * 64; u += 256) g_pool[u] = 0.0f;
        if (t < BB) g_cnti[t] = 0;
        if (t == 0) { m3_c = 0; m3_c2 = 0; m3_f = 0; }
        __threadfence();
    }
}

extern "C" void kernel_launch(void* const* d_in, const int* in_sizes, int n_in,
                              void* d_out, int out_size) {
    const float* x     = (const float*)d_in[0];
    const void*  ei    = d_in[1];
    const void*  batch = d_in[2];
    const float* W1 = (const float*)d_in[3];
    const float* b1 = (const float*)d_in[4];
    const float* g1 = (const float*)d_in[5];
    const float* be1 = (const float*)d_in[6];
    const float* W2 = (const float*)d_in[7];
    const float* b2 = (const float*)d_in[8];
    const float* g2 = (const float*)d_in[9];
    const float* be2 = (const float*)d_in[10];
    const float* W3 = (const float*)d_in[11];
    const float* b3 = (const float*)d_in[12];
    const float* g3 = (const float*)d_in[13];
    const float* be3 = (const float*)d_in[14];
    const float* fcW = (const float*)d_in[15];
    const float* fcb = (const float*)d_in[16];
    float* out = (float*)d_out;

    csr_kernel<<<592, 256>>>(ei, batch, x);
    layer1_kernel<<<391, 256>>>(W1, b1, g1, be1);
    gather_bf16_kernel<16><<<(NN * 2 + 255) / 256, 256>>>();
    momfused2_kernel<<<592, 256>>>(W2, b2, g2, be2);
    gather_bf16_kernel<32><<<(NN * 4 + 255) / 256, 256>>>();
    momfused3_kernel<<<592, 256>>>(W3, b3, g3, be3, fcW, fcb, out);
}